// round 10
// baseline (speedup 1.0000x reference)
#include <cuda_runtime.h>
#include <cuda_bf16.h>
#include <math.h>

#define B_ 64
#define W_ 4096
#define H_ 128
#define I_ 128
#define CHUNKS 8
#define TPB (W_ / CHUNKS)
#define WARPS 8
#define ROWS_PER_WARP (TPB / WARPS)
#define TAIL_BLOCKS 128

__device__ float g_pm[B_ * CHUNKS];
__device__ float g_pl[B_ * CHUNKS];
__device__ float g_pacc[B_ * CHUNKS * H_];

// Transposed activations [k][b]
__device__ float g_xcatT[(H_ + I_) * B_];
__device__ float g_xinT[I_ * B_];
__device__ float g_h1T[H_ * B_];
__device__ float g_h0T0[H_ * B_];
__device__ float g_h0T1[H_ * B_];

// Monotonic grid-barrier counters (zero-init at load; monotonic across replays)
__device__ unsigned g_bar[4];

__device__ __forceinline__ void grid_barrier(int idx) {
    __syncthreads();
    if (threadIdx.x == 0) {
        __threadfence();                                   // release
        unsigned old = atomicAdd(&g_bar[idx], 1u);
        unsigned target = old - (old % TAIL_BLOCKS) + TAIL_BLOCKS;
        while ((int)(*(volatile unsigned*)&g_bar[idx] - target) < 0) { }
    }
    __syncthreads();
    __threadfence();                                       // acquire
}

__device__ __forceinline__ float warp_sum(float v) {
    #pragma unroll
    for (int o = 16; o; o >>= 1) v += __shfl_xor_sync(0xffffffffu, v, o);
    return v;
}

__device__ __forceinline__ float sigm(float x) { return 1.0f / (1.0f + expf(-x)); }

// ---------------------------------------------------------------------------
// Phase 1: fused score + online-softmax weighted accumulate (1 encoder pass).
// 2 rows per iteration (Round-9 winner, unchanged).
// ---------------------------------------------------------------------------
__global__ __launch_bounds__(256, 4)
void attn_partial_kernel(const float* __restrict__ enc,
                         const float* __restrict__ h0,
                         const float* __restrict__ c0,
                         const float* __restrict__ attW,
                         const float* __restrict__ attB)
{
    const int c    = blockIdx.x;
    const int b    = blockIdx.y;
    const int tid  = threadIdx.x;
    const int warp = tid >> 5;
    const int lane = tid & 31;

    __shared__ float s_red[WARPS];
    __shared__ float s_bias;
    __shared__ float s_m[WARPS], s_l[WARPS];
    __shared__ float s_acc[WARPS][H_];

    float part = 0.f;
    if (tid < H_) {
        float hs = h0[(1 * B_ + b) * H_ + tid];
        float cs = c0[(1 * B_ + b) * H_ + tid];
        part = hs * cs * attW[H_ + tid];
    }
    part = warp_sum(part);
    if (lane == 0) s_red[warp] = part;
    __syncthreads();
    if (tid == 0) {
        float s = 0.f;
        #pragma unroll
        for (int w = 0; w < WARPS; w++) s += s_red[w];
        s_bias = s + attB[0];
    }
    __syncthreads();
    const float bias = s_bias;

    const float4 wa = *reinterpret_cast<const float4*>(attW + lane * 4);

    const int rowStart = c * TPB + warp * ROWS_PER_WARP;
    const float* encb = enc + (size_t)b * W_ * H_;

    float prevLogit;
    if (rowStart == 0) {
        prevLogit = 0.0f;
    } else {
        float4 v = *reinterpret_cast<const float4*>(
            encb + (size_t)(rowStart - 1) * H_ + lane * 4);
        float d = v.x * wa.x + v.y * wa.y + v.z * wa.z + v.w * wa.w;
        d = warp_sum(d);
        prevLogit = d + bias;
    }

    float m = -1e30f, l = 0.f;
    float ax = 0.f, ay = 0.f, az = 0.f, aw = 0.f;

    const float* rp = encb + (size_t)rowStart * H_ + lane * 4;
    #pragma unroll 4
    for (int it = 0; it < ROWS_PER_WARP / 2; it++) {
        const float4 v0 = *reinterpret_cast<const float4*>(rp);
        const float4 v1 = *reinterpret_cast<const float4*>(rp + H_);
        rp += 2 * H_;
        float d0 = v0.x * wa.x + v0.y * wa.y + v0.z * wa.z + v0.w * wa.w;
        float d1 = v1.x * wa.x + v1.y * wa.y + v1.z * wa.z + v1.w * wa.w;
        #pragma unroll
        for (int o = 16; o; o >>= 1) {
            d0 += __shfl_xor_sync(0xffffffffu, d0, o);
            d1 += __shfl_xor_sync(0xffffffffu, d1, o);
        }
        const float logit0 = prevLogit;
        const float logit1 = d0 + bias;
        prevLogit = d1 + bias;
        const float mNew = fmaxf(m, fmaxf(logit0, logit1));
        const float corr = __expf(m - mNew);
        const float p0   = __expf(logit0 - mNew);
        const float p1   = __expf(logit1 - mNew);
        l  = l * corr + p0 + p1;
        ax = ax * corr + p0 * v0.x + p1 * v1.x;
        ay = ay * corr + p0 * v0.y + p1 * v1.y;
        az = az * corr + p0 * v0.z + p1 * v1.z;
        aw = aw * corr + p0 * v0.w + p1 * v1.w;
        m = mNew;
    }

    if (lane == 0) { s_m[warp] = m; s_l[warp] = l; }
    s_acc[warp][lane * 4 + 0] = ax;
    s_acc[warp][lane * 4 + 1] = ay;
    s_acc[warp][lane * 4 + 2] = az;
    s_acc[warp][lane * 4 + 3] = aw;
    __syncthreads();

    if (tid < H_) {
        float M = s_m[0];
        #pragma unroll
        for (int w = 1; w < WARPS; w++) M = fmaxf(M, s_m[w]);
        float L = 0.f, A = 0.f;
        #pragma unroll
        for (int w = 0; w < WARPS; w++) {
            const float e = __expf(s_m[w] - M);
            L += s_l[w] * e;
            A += s_acc[w][tid] * e;
        }
        const int pi = b * CHUNKS + c;
        g_pacc[pi * H_ + tid] = A;
        if (tid == 0) { g_pm[pi] = M; g_pl[pi] = L; }
    }
}

// ---------------------------------------------------------------------------
// Fused tail: combine -> xin -> LSTM0 -> LSTM1 in ONE kernel.
// grid = 128 blocks x 512 threads, single wave (<=148 SMs) -> software grid
// barriers are safe. Inner loop bodies are the Round-8/9 proven versions.
// out layout: [h2 (B,H)] [h1] [h2] [c1] [c2]
// ---------------------------------------------------------------------------
__device__ __forceinline__ void lstm_step(
    int h, int tid,
    const float* __restrict__ xT, const float* __restrict__ hT,
    const float* __restrict__ W_ih, const float* __restrict__ W_hh,
    const float* __restrict__ b_ih, const float* __restrict__ b_hh,
    const float* __restrict__ cPrev,
    float* __restrict__ outH, float* __restrict__ outH2,
    float* __restrict__ outC, float* __restrict__ hT_out,
    float (*s_w)[2 * H_], float (*s_part)[4][B_])
{
    const int b     = tid & 63;
    const int gate  = (tid >> 6) & 3;
    const int khalf = tid >> 8;
    const int j     = gate * H_ + h;

    #pragma unroll
    for (int i = tid; i < 4 * 2 * H_; i += 512) {
        const int g = i >> 8;
        const int k = i & 255;
        s_w[g][k] = (k < H_) ? W_ih[(g * H_ + h) * H_ + k]
                             : W_hh[(g * H_ + h) * H_ + (k - H_)];
    }
    __syncthreads();

    const float* wp = &s_w[gate][khalf * H_];
    const float* ap = (khalf == 0) ? xT : hT;
    float acc = (khalf == 0) ? b_ih[j] : b_hh[j];
    #pragma unroll
    for (int kk = 0; kk < H_; kk += 8) {
        float v0 = ap[(kk + 0) * B_ + b];
        float v1 = ap[(kk + 1) * B_ + b];
        float v2 = ap[(kk + 2) * B_ + b];
        float v3 = ap[(kk + 3) * B_ + b];
        float v4 = ap[(kk + 4) * B_ + b];
        float v5 = ap[(kk + 5) * B_ + b];
        float v6 = ap[(kk + 6) * B_ + b];
        float v7 = ap[(kk + 7) * B_ + b];
        acc = fmaf(wp[kk + 0], v0, acc);
        acc = fmaf(wp[kk + 1], v1, acc);
        acc = fmaf(wp[kk + 2], v2, acc);
        acc = fmaf(wp[kk + 3], v3, acc);
        acc = fmaf(wp[kk + 4], v4, acc);
        acc = fmaf(wp[kk + 5], v5, acc);
        acc = fmaf(wp[kk + 6], v6, acc);
        acc = fmaf(wp[kk + 7], v7, acc);
    }
    s_part[khalf][gate][b] = acc;
    __syncthreads();

    if (tid < B_) {
        const int bb = tid;
        const float gi = s_part[0][0][bb] + s_part[1][0][bb];
        const float gf = s_part[0][1][bb] + s_part[1][1][bb];
        const float gg = s_part[0][2][bb] + s_part[1][2][bb];
        const float go = s_part[0][3][bb] + s_part[1][3][bb];
        const float cp = cPrev[bb * H_ + h];
        const float cN = sigm(gf) * cp + sigm(gi) * tanhf(gg);
        const float hN = sigm(go) * tanhf(cN);
        outH[bb * H_ + h] = hN;
        if (outH2) outH2[bb * H_ + h] = hN;
        outC[bb * H_ + h] = cN;
        if (hT_out) hT_out[h * B_ + bb] = hN;
    }
}

__global__ __launch_bounds__(512, 1)
void tail_fused_kernel(const float* __restrict__ input,
                       const float* __restrict__ h0,
                       const float* __restrict__ c0,
                       const float* __restrict__ inp_W,
                       const float* __restrict__ inp_b,
                       const float* __restrict__ W_ih0,
                       const float* __restrict__ W_hh0,
                       const float* __restrict__ b_ih0,
                       const float* __restrict__ b_hh0,
                       const float* __restrict__ W_ih1,
                       const float* __restrict__ W_hh1,
                       const float* __restrict__ b_ih1,
                       const float* __restrict__ b_hh1,
                       float* __restrict__ out)
{
    const int blk = blockIdx.x;
    const int tid = threadIdx.x;

    __shared__ float s_w[4][2 * H_];       // reused: xin weights / lstm weights
    __shared__ float s_part[2][4][B_];     // reused partials
    __shared__ float s_xp[8][B_];          // xin partials [kseg][b]

    // ---- Step A: combine (blocks 0..63, threads 0..255) ----
    if (blk < B_ && tid < H_ + I_) {
        const int b = blk;
        const int k = tid;
        if (k < H_) {
            float M = g_pm[b * CHUNKS + 0];
            #pragma unroll
            for (int cc = 1; cc < CHUNKS; cc++) M = fmaxf(M, g_pm[b * CHUNKS + cc]);
            float L = 0.f, A = 0.f;
            #pragma unroll
            for (int cc = 0; cc < CHUNKS; cc++) {
                const float e = __expf(g_pm[b * CHUNKS + cc] - M);
                L += g_pl[b * CHUNKS + cc] * e;
                A += g_pacc[(b * CHUNKS + cc) * H_ + k] * e;
            }
            g_xcatT[k * B_ + b] = A / L;
            g_h0T0[k * B_ + b] = h0[(0 * B_ + b) * H_ + k];
            g_h0T1[k * B_ + b] = h0[(1 * B_ + b) * H_ + k];
        } else {
            g_xcatT[k * B_ + b] = input[b * I_ + (k - H_)];
        }
    }
    grid_barrier(0);

    // ---- Step B: xin. block = j (128), 512 threads: b = tid&63, kseg = tid>>6 ----
    {
        const int j    = blk;
        const int b    = tid & 63;
        const int kseg = tid >> 6;      // 8 segments x 32 k

        // stage weight row j (256 floats)
        if (tid < H_ + I_) s_w[0][tid] = inp_W[j * (H_ + I_) + tid];
        __syncthreads();

        const float* wp = &s_w[0][kseg * 32];
        const float* ap = &g_xcatT[kseg * 32 * B_];
        float acc = 0.f;
        #pragma unroll
        for (int kk = 0; kk < 32; kk += 8) {
            float v0 = ap[(kk + 0) * B_ + b];
            float v1 = ap[(kk + 1) * B_ + b];
            float v2 = ap[(kk + 2) * B_ + b];
            float v3 = ap[(kk + 3) * B_ + b];
            float v4 = ap[(kk + 4) * B_ + b];
            float v5 = ap[(kk + 5) * B_ + b];
            float v6 = ap[(kk + 6) * B_ + b];
            float v7 = ap[(kk + 7) * B_ + b];
            acc = fmaf(wp[kk + 0], v0, acc);
            acc = fmaf(wp[kk + 1], v1, acc);
            acc = fmaf(wp[kk + 2], v2, acc);
            acc = fmaf(wp[kk + 3], v3, acc);
            acc = fmaf(wp[kk + 4], v4, acc);
            acc = fmaf(wp[kk + 5], v5, acc);
            acc = fmaf(wp[kk + 6], v6, acc);
            acc = fmaf(wp[kk + 7], v7, acc);
        }
        s_xp[kseg][b] = acc;
        __syncthreads();

        if (tid < B_) {
            float s = inp_b[j];
            #pragma unroll
            for (int q = 0; q < 8; q++) s += s_xp[q][tid];
            g_xinT[j * B_ + tid] = s;
        }
    }
    grid_barrier(1);

    // ---- Step C: LSTM layer 0 (block = h) ----
    lstm_step(blk, tid, g_xinT, g_h0T0, W_ih0, W_hh0, b_ih0, b_hh0,
              c0 + 0 * B_ * H_,
              out + 1 * B_ * H_, nullptr, out + 3 * B_ * H_, g_h1T,
              s_w, s_part);
    grid_barrier(2);

    // ---- Step D: LSTM layer 1 (block = h) ----
    lstm_step(blk, tid, g_h1T, g_h0T1, W_ih1, W_hh1, b_ih1, b_hh1,
              c0 + 1 * B_ * H_,
              out + 0 * B_ * H_, out + 2 * B_ * H_, out + 4 * B_ * H_, nullptr,
              s_w, s_part);
}

extern "C" void kernel_launch(void* const* d_in, const int* in_sizes, int n_in,
                              void* d_out, int out_size) {
    const float* input  = (const float*)d_in[0];
    const float* h0     = (const float*)d_in[1];
    const float* c0     = (const float*)d_in[2];
    const float* enc    = (const float*)d_in[3];
    const float* attW   = (const float*)d_in[4];
    const float* attB   = (const float*)d_in[5];
    const float* inp_W  = (const float*)d_in[6];
    const float* inp_b  = (const float*)d_in[7];
    const float* W_ih0  = (const float*)d_in[8];
    const float* W_hh0  = (const float*)d_in[9];
    const float* b_ih0  = (const float*)d_in[10];
    const float* b_hh0  = (const float*)d_in[11];
    const float* W_ih1  = (const float*)d_in[12];
    const float* W_hh1  = (const float*)d_in[13];
    const float* b_ih1  = (const float*)d_in[14];
    const float* b_hh1  = (const float*)d_in[15];
    float* out = (float*)d_out;

    dim3 grid1(CHUNKS, B_);
    attn_partial_kernel<<<grid1, 256>>>(enc, h0, c0, attW, attB);
    tail_fused_kernel<<<TAIL_BLOCKS, 512>>>(input, h0, c0, inp_W, inp_b,
                                            W_ih0, W_hh0, b_ih0, b_hh0,
                                            W_ih1, W_hh1, b_ih1, b_hh1, out);
}

// round 11
// speedup vs baseline: 1.0929x; 1.0929x over previous
#include <cuda_runtime.h>
#include <cuda_bf16.h>
#include <math.h>

#define B_ 64
#define W_ 4096
#define H_ 128
#define I_ 128
#define CHUNKS 8
#define TPB (W_ / CHUNKS)
#define WARPS 8
#define ROWS_PER_WARP (TPB / WARPS)
#define TAIL_BLOCKS 128

__device__ float g_pm[B_ * CHUNKS];
__device__ float g_pl[B_ * CHUNKS];
__device__ float g_pacc[B_ * CHUNKS * H_];

// Transposed activations [k][b]
__device__ float g_xcatT[(H_ + I_) * B_];
__device__ float g_xinT[I_ * B_];
__device__ float g_h1T[H_ * B_];
__device__ float g_h0T0[H_ * B_];
__device__ float g_h0T1[H_ * B_];

// Monotonic grid-barrier counters (zero-init at load; monotonic across replays)
__device__ unsigned g_bar[4];

__device__ __forceinline__ void grid_barrier(int idx) {
    __syncthreads();
    if (threadIdx.x == 0) {
        __threadfence();                                   // release
        unsigned old = atomicAdd(&g_bar[idx], 1u);
        unsigned target = old - (old % TAIL_BLOCKS) + TAIL_BLOCKS;
        while ((int)(*(volatile unsigned*)&g_bar[idx] - target) < 0) { }
    }
    __syncthreads();
    __threadfence();                                       // acquire
}

__device__ __forceinline__ float warp_sum(float v) {
    #pragma unroll
    for (int o = 16; o; o >>= 1) v += __shfl_xor_sync(0xffffffffu, v, o);
    return v;
}

__device__ __forceinline__ float sigm(float x) { return 1.0f / (1.0f + expf(-x)); }

// ---------------------------------------------------------------------------
// Phase 1: fused score + online-softmax weighted accumulate (1 encoder pass).
// v3: 4 rows per iteration — 4 independent LDG.128/lane (per-SM outstanding
// bytes ~ BW*latency product), 4 interleaved SHFL reduce chains, one combined
// softmax rescale per quad. __ldcs streaming hints (no reuse).
// ---------------------------------------------------------------------------
__global__ __launch_bounds__(256, 4)
void attn_partial_kernel(const float* __restrict__ enc,
                         const float* __restrict__ h0,
                         const float* __restrict__ c0,
                         const float* __restrict__ attW,
                         const float* __restrict__ attB)
{
    const int c    = blockIdx.x;
    const int b    = blockIdx.y;
    const int tid  = threadIdx.x;
    const int warp = tid >> 5;
    const int lane = tid & 31;

    __shared__ float s_red[WARPS];
    __shared__ float s_bias;
    __shared__ float s_m[WARPS], s_l[WARPS];
    __shared__ float s_acc[WARPS][H_];

    float part = 0.f;
    if (tid < H_) {
        float hs = h0[(1 * B_ + b) * H_ + tid];
        float cs = c0[(1 * B_ + b) * H_ + tid];
        part = hs * cs * attW[H_ + tid];
    }
    part = warp_sum(part);
    if (lane == 0) s_red[warp] = part;
    __syncthreads();
    if (tid == 0) {
        float s = 0.f;
        #pragma unroll
        for (int w = 0; w < WARPS; w++) s += s_red[w];
        s_bias = s + attB[0];
    }
    __syncthreads();
    const float bias = s_bias;

    const float4 wa = *reinterpret_cast<const float4*>(attW + lane * 4);

    const int rowStart = c * TPB + warp * ROWS_PER_WARP;
    const float* encb = enc + (size_t)b * W_ * H_;

    float prevLogit;
    if (rowStart == 0) {
        prevLogit = 0.0f;
    } else {
        float4 v = __ldcs(reinterpret_cast<const float4*>(
            encb + (size_t)(rowStart - 1) * H_ + lane * 4));
        float d = v.x * wa.x + v.y * wa.y + v.z * wa.z + v.w * wa.w;
        d = warp_sum(d);
        prevLogit = d + bias;
    }

    float m = -1e30f, l = 0.f;
    float ax = 0.f, ay = 0.f, az = 0.f, aw = 0.f;

    const float* rp = encb + (size_t)rowStart * H_ + lane * 4;
    #pragma unroll 2
    for (int it = 0; it < ROWS_PER_WARP / 4; it++) {
        const float4 v0 = __ldcs(reinterpret_cast<const float4*>(rp));
        const float4 v1 = __ldcs(reinterpret_cast<const float4*>(rp + H_));
        const float4 v2 = __ldcs(reinterpret_cast<const float4*>(rp + 2 * H_));
        const float4 v3 = __ldcs(reinterpret_cast<const float4*>(rp + 3 * H_));
        rp += 4 * H_;
        float d0 = v0.x * wa.x + v0.y * wa.y + v0.z * wa.z + v0.w * wa.w;
        float d1 = v1.x * wa.x + v1.y * wa.y + v1.z * wa.z + v1.w * wa.w;
        float d2 = v2.x * wa.x + v2.y * wa.y + v2.z * wa.z + v2.w * wa.w;
        float d3 = v3.x * wa.x + v3.y * wa.y + v3.z * wa.z + v3.w * wa.w;
        #pragma unroll
        for (int o = 16; o; o >>= 1) {
            d0 += __shfl_xor_sync(0xffffffffu, d0, o);
            d1 += __shfl_xor_sync(0xffffffffu, d1, o);
            d2 += __shfl_xor_sync(0xffffffffu, d2, o);
            d3 += __shfl_xor_sync(0xffffffffu, d3, o);
        }
        const float l0 = prevLogit;
        const float l1 = d0 + bias;
        const float l2 = d1 + bias;
        const float l3 = d2 + bias;
        prevLogit = d3 + bias;
        const float mNew = fmaxf(fmaxf(m, fmaxf(l0, l1)), fmaxf(l2, l3));
        const float corr = __expf(m - mNew);
        const float p0   = __expf(l0 - mNew);
        const float p1   = __expf(l1 - mNew);
        const float p2   = __expf(l2 - mNew);
        const float p3   = __expf(l3 - mNew);
        l  = l * corr + p0 + p1 + p2 + p3;
        ax = ax * corr + p0 * v0.x + p1 * v1.x + p2 * v2.x + p3 * v3.x;
        ay = ay * corr + p0 * v0.y + p1 * v1.y + p2 * v2.y + p3 * v3.y;
        az = az * corr + p0 * v0.z + p1 * v1.z + p2 * v2.z + p3 * v3.z;
        aw = aw * corr + p0 * v0.w + p1 * v1.w + p2 * v2.w + p3 * v3.w;
        m = mNew;
    }

    if (lane == 0) { s_m[warp] = m; s_l[warp] = l; }
    s_acc[warp][lane * 4 + 0] = ax;
    s_acc[warp][lane * 4 + 1] = ay;
    s_acc[warp][lane * 4 + 2] = az;
    s_acc[warp][lane * 4 + 3] = aw;
    __syncthreads();

    if (tid < H_) {
        float M = s_m[0];
        #pragma unroll
        for (int w = 1; w < WARPS; w++) M = fmaxf(M, s_m[w]);
        float L = 0.f, A = 0.f;
        #pragma unroll
        for (int w = 0; w < WARPS; w++) {
            const float e = __expf(s_m[w] - M);
            L += s_l[w] * e;
            A += s_acc[w][tid] * e;
        }
        const int pi = b * CHUNKS + c;
        g_pacc[pi * H_ + tid] = A;
        if (tid == 0) { g_pm[pi] = M; g_pl[pi] = L; }
    }
}

// ---------------------------------------------------------------------------
// Fused tail with smem-resident activations.
// Dynamic smem layout (floats):
//   s_act [16384]  — 64 KB activation staging (xcat | xT+hT)
//   s_w   [1024]   — weight rows
//   s_part[512]    — partials [khalf][gate][b]
//   s_xp  [512]    — xin partials [kseg][b]
// ---------------------------------------------------------------------------
#define SM_ACT  0
#define SM_W    16384
#define SM_PART 17408
#define SM_XP   17920
#define SM_TOTAL_FLOATS 18432   // 72 KB

// stage `n` floats from gsrc to s_act+off, coalesced float4, 512 threads
__device__ __forceinline__ void stage_act(float* s, const float* __restrict__ gsrc,
                                          int off, int n, int tid) {
    float4* d = reinterpret_cast<float4*>(s + off);
    const float4* g = reinterpret_cast<const float4*>(gsrc);
    const int n4 = n >> 2;
    #pragma unroll
    for (int i = tid; i < n4; i += 512) d[i] = g[i];
}

__device__ __forceinline__ void lstm_step(
    int h, int tid, float* smem,
    const float* __restrict__ xT, const float* __restrict__ hT,   // global
    const float* __restrict__ W_ih, const float* __restrict__ W_hh,
    const float* __restrict__ b_ih, const float* __restrict__ b_hh,
    const float* __restrict__ cPrev,
    float* __restrict__ outH, float* __restrict__ outH2,
    float* __restrict__ outC, float* __restrict__ hT_out)
{
    const int b     = tid & 63;
    const int gate  = (tid >> 6) & 3;
    const int khalf = tid >> 8;
    const int j     = gate * H_ + h;

    float* s_act  = smem + SM_ACT;
    float* s_w    = smem + SM_W;
    float* s_part = smem + SM_PART;

    // stage activations (32 KB each) + weights
    stage_act(smem, xT, SM_ACT,         H_ * B_, tid);
    stage_act(smem, hT, SM_ACT + H_ * B_, H_ * B_, tid);
    #pragma unroll
    for (int i = tid; i < 4 * 2 * H_; i += 512) {
        const int g = i >> 8;
        const int k = i & 255;
        s_w[g * 2 * H_ + k] = (k < H_) ? W_ih[(g * H_ + h) * H_ + k]
                                       : W_hh[(g * H_ + h) * H_ + (k - H_)];
    }
    __syncthreads();

    const float* wp = s_w + gate * 2 * H_ + khalf * H_;
    const float* ap = s_act + khalf * (H_ * B_) + b;
    float acc = (khalf == 0) ? b_ih[j] : b_hh[j];
    #pragma unroll
    for (int kk = 0; kk < H_; kk += 8) {
        float v0 = ap[(kk + 0) * B_];
        float v1 = ap[(kk + 1) * B_];
        float v2 = ap[(kk + 2) * B_];
        float v3 = ap[(kk + 3) * B_];
        float v4 = ap[(kk + 4) * B_];
        float v5 = ap[(kk + 5) * B_];
        float v6 = ap[(kk + 6) * B_];
        float v7 = ap[(kk + 7) * B_];
        acc = fmaf(wp[kk + 0], v0, acc);
        acc = fmaf(wp[kk + 1], v1, acc);
        acc = fmaf(wp[kk + 2], v2, acc);
        acc = fmaf(wp[kk + 3], v3, acc);
        acc = fmaf(wp[kk + 4], v4, acc);
        acc = fmaf(wp[kk + 5], v5, acc);
        acc = fmaf(wp[kk + 6], v6, acc);
        acc = fmaf(wp[kk + 7], v7, acc);
    }
    s_part[(khalf * 4 + gate) * B_ + b] = acc;
    __syncthreads();

    if (tid < B_) {
        const int bb = tid;
        const float gi = s_part[(0 * 4 + 0) * B_ + bb] + s_part[(1 * 4 + 0) * B_ + bb];
        const float gf = s_part[(0 * 4 + 1) * B_ + bb] + s_part[(1 * 4 + 1) * B_ + bb];
        const float gg = s_part[(0 * 4 + 2) * B_ + bb] + s_part[(1 * 4 + 2) * B_ + bb];
        const float go = s_part[(0 * 4 + 3) * B_ + bb] + s_part[(1 * 4 + 3) * B_ + bb];
        const float cp = cPrev[bb * H_ + h];
        const float cN = sigm(gf) * cp + sigm(gi) * tanhf(gg);
        const float hN = sigm(go) * tanhf(cN);
        outH[bb * H_ + h] = hN;
        if (outH2) outH2[bb * H_ + h] = hN;
        outC[bb * H_ + h] = cN;
        if (hT_out) hT_out[h * B_ + bb] = hN;
    }
}

__global__ __launch_bounds__(512, 1)
void tail_fused_kernel(const float* __restrict__ input,
                       const float* __restrict__ h0,
                       const float* __restrict__ c0,
                       const float* __restrict__ inp_W,
                       const float* __restrict__ inp_b,
                       const float* __restrict__ W_ih0,
                       const float* __restrict__ W_hh0,
                       const float* __restrict__ b_ih0,
                       const float* __restrict__ b_hh0,
                       const float* __restrict__ W_ih1,
                       const float* __restrict__ W_hh1,
                       const float* __restrict__ b_ih1,
                       const float* __restrict__ b_hh1,
                       float* __restrict__ out)
{
    extern __shared__ float smem[];
    const int blk = blockIdx.x;
    const int tid = threadIdx.x;

    float* s_act = smem + SM_ACT;
    float* s_w   = smem + SM_W;
    float* s_xp  = smem + SM_XP;

    // ---- Step A: combine (blocks 0..63, threads 0..255) ----
    if (blk < B_ && tid < H_ + I_) {
        const int b = blk;
        const int k = tid;
        if (k < H_) {
            float M = g_pm[b * CHUNKS + 0];
            #pragma unroll
            for (int cc = 1; cc < CHUNKS; cc++) M = fmaxf(M, g_pm[b * CHUNKS + cc]);
            float L = 0.f, A = 0.f;
            #pragma unroll
            for (int cc = 0; cc < CHUNKS; cc++) {
                const float e = __expf(g_pm[b * CHUNKS + cc] - M);
                L += g_pl[b * CHUNKS + cc] * e;
                A += g_pacc[(b * CHUNKS + cc) * H_ + k] * e;
            }
            g_xcatT[k * B_ + b] = A / L;
            g_h0T0[k * B_ + b] = h0[(0 * B_ + b) * H_ + k];
            g_h0T1[k * B_ + b] = h0[(1 * B_ + b) * H_ + k];
        } else {
            g_xcatT[k * B_ + b] = input[b * I_ + (k - H_)];
        }
    }
    grid_barrier(0);

    // ---- Step B: xin from smem-staged xcat. block = j, 512 threads ----
    {
        const int j    = blk;
        const int b    = tid & 63;
        const int kseg = tid >> 6;      // 8 segments x 32 k

        stage_act(smem, g_xcatT, SM_ACT, (H_ + I_) * B_, tid);
        if (tid < H_ + I_) s_w[tid] = inp_W[j * (H_ + I_) + tid];
        __syncthreads();

        const float* wp = s_w + kseg * 32;
        const float* ap = s_act + kseg * 32 * B_ + b;
        float acc = 0.f;
        #pragma unroll
        for (int kk = 0; kk < 32; kk += 8) {
            float v0 = ap[(kk + 0) * B_];
            float v1 = ap[(kk + 1) * B_];
            float v2 = ap[(kk + 2) * B_];
            float v3 = ap[(kk + 3) * B_];
            float v4 = ap[(kk + 4) * B_];
            float v5 = ap[(kk + 5) * B_];
            float v6 = ap[(kk + 6) * B_];
            float v7 = ap[(kk + 7) * B_];
            acc = fmaf(wp[kk + 0], v0, acc);
            acc = fmaf(wp[kk + 1], v1, acc);
            acc = fmaf(wp[kk + 2], v2, acc);
            acc = fmaf(wp[kk + 3], v3, acc);
            acc = fmaf(wp[kk + 4], v4, acc);
            acc = fmaf(wp[kk + 5], v5, acc);
            acc = fmaf(wp[kk + 6], v6, acc);
            acc = fmaf(wp[kk + 7], v7, acc);
        }
        s_xp[kseg * B_ + b] = acc;
        __syncthreads();

        if (tid < B_) {
            float s = inp_b[j];
            #pragma unroll
            for (int q = 0; q < 8; q++) s += s_xp[q * B_ + tid];
            g_xinT[j * B_ + tid] = s;
        }
    }
    grid_barrier(1);

    // ---- Step C: LSTM layer 0 (block = h) ----
    lstm_step(blk, tid, smem, g_xinT, g_h0T0, W_ih0, W_hh0, b_ih0, b_hh0,
              c0 + 0 * B_ * H_,
              out + 1 * B_ * H_, nullptr, out + 3 * B_ * H_, g_h1T);
    grid_barrier(2);

    // ---- Step D: LSTM layer 1 (block = h) ----
    lstm_step(blk, tid, smem, g_h1T, g_h0T1, W_ih1, W_hh1, b_ih1, b_hh1,
              c0 + 1 * B_ * H_,
              out + 0 * B_ * H_, out + 2 * B_ * H_, out + 4 * B_ * H_, nullptr);
}

extern "C" void kernel_launch(void* const* d_in, const int* in_sizes, int n_in,
                              void* d_out, int out_size) {
    const float* input  = (const float*)d_in[0];
    const float* h0     = (const float*)d_in[1];
    const float* c0     = (const float*)d_in[2];
    const float* enc    = (const float*)d_in[3];
    const float* attW   = (const float*)d_in[4];
    const float* attB   = (const float*)d_in[5];
    const float* inp_W  = (const float*)d_in[6];
    const float* inp_b  = (const float*)d_in[7];
    const float* W_ih0  = (const float*)d_in[8];
    const float* W_hh0  = (const float*)d_in[9];
    const float* b_ih0  = (const float*)d_in[10];
    const float* b_hh0  = (const float*)d_in[11];
    const float* W_ih1  = (const float*)d_in[12];
    const float* W_hh1  = (const float*)d_in[13];
    const float* b_ih1  = (const float*)d_in[14];
    const float* b_hh1  = (const float*)d_in[15];
    float* out = (float*)d_out;

    static int smem_set = 0;
    if (!smem_set) {
        cudaFuncSetAttribute(tail_fused_kernel,
                             cudaFuncAttributeMaxDynamicSharedMemorySize,
                             SM_TOTAL_FLOATS * 4);
        smem_set = 1;
    }

    dim3 grid1(CHUNKS, B_);
    attn_partial_kernel<<<grid1, 256>>>(enc, h0, c0, attW, attB);
    tail_fused_kernel<<<TAIL_BLOCKS, 512, SM_TOTAL_FLOATS * 4>>>(
        input, h0, c0, inp_W, inp_b,
        W_ih0, W_hh0, b_ih0, b_hh0,
        W_ih1, W_hh1, b_ih1, b_hh1, out);
}

// round 14
// speedup vs baseline: 1.1275x; 1.0317x over previous
#include <cuda_runtime.h>
#include <cuda_bf16.h>
#include <math.h>

#define B_ 64
#define W_ 4096
#define H_ 128
#define I_ 128
#define CHUNKS 8
#define TPB (W_ / CHUNKS)
#define WARPS 8
#define ROWS_PER_WARP (TPB / WARPS)
#define TAIL_BLOCKS 128

__device__ float g_pm[B_ * CHUNKS];
__device__ float g_pl[B_ * CHUNKS];
__device__ float g_pacc[B_ * CHUNKS * H_];

// Transposed activations [k][b]
__device__ float g_xcatT[(H_ + I_) * B_];
__device__ float g_xinT[I_ * B_];
__device__ float g_h1T[H_ * B_];
__device__ float g_h0T0[H_ * B_];
__device__ float g_h0T1[H_ * B_];

// Monotonic grid-barrier counters (zero-init at load; monotonic across replays)
__device__ unsigned g_bar[4];

__device__ __forceinline__ void grid_barrier(int idx) {
    __syncthreads();
    if (threadIdx.x == 0) {
        __threadfence();                                   // release
        unsigned old = atomicAdd(&g_bar[idx], 1u);
        unsigned target = old - (old % TAIL_BLOCKS) + TAIL_BLOCKS;
        while ((int)(*(volatile unsigned*)&g_bar[idx] - target) < 0) { }
    }
    __syncthreads();
    __threadfence();                                       // acquire
}

__device__ __forceinline__ float warp_sum(float v) {
    #pragma unroll
    for (int o = 16; o; o >>= 1) v += __shfl_xor_sync(0xffffffffu, v, o);
    return v;
}

__device__ __forceinline__ float sigm(float x) { return 1.0f / (1.0f + expf(-x)); }

// ---------------------------------------------------------------------------
// Phase 1: fused score + online-softmax weighted accumulate (1 encoder pass).
// v3 (Round-11 winner, unchanged): 4 rows/iter, __ldcs streaming.
// ---------------------------------------------------------------------------
__global__ __launch_bounds__(256, 4)
void attn_partial_kernel(const float* __restrict__ enc,
                         const float* __restrict__ h0,
                         const float* __restrict__ c0,
                         const float* __restrict__ attW,
                         const float* __restrict__ attB)
{
    const int c    = blockIdx.x;
    const int b    = blockIdx.y;
    const int tid  = threadIdx.x;
    const int warp = tid >> 5;
    const int lane = tid & 31;

    __shared__ float s_red[WARPS];
    __shared__ float s_bias;
    __shared__ float s_m[WARPS], s_l[WARPS];
    __shared__ float s_acc[WARPS][H_];

    float part = 0.f;
    if (tid < H_) {
        float hs = h0[(1 * B_ + b) * H_ + tid];
        float cs = c0[(1 * B_ + b) * H_ + tid];
        part = hs * cs * attW[H_ + tid];
    }
    part = warp_sum(part);
    if (lane == 0) s_red[warp] = part;
    __syncthreads();
    if (tid == 0) {
        float s = 0.f;
        #pragma unroll
        for (int w = 0; w < WARPS; w++) s += s_red[w];
        s_bias = s + attB[0];
    }
    __syncthreads();
    const float bias = s_bias;

    const float4 wa = *reinterpret_cast<const float4*>(attW + lane * 4);

    const int rowStart = c * TPB + warp * ROWS_PER_WARP;
    const float* encb = enc + (size_t)b * W_ * H_;

    float prevLogit;
    if (rowStart == 0) {
        prevLogit = 0.0f;
    } else {
        float4 v = __ldcs(reinterpret_cast<const float4*>(
            encb + (size_t)(rowStart - 1) * H_ + lane * 4));
        float d = v.x * wa.x + v.y * wa.y + v.z * wa.z + v.w * wa.w;
        d = warp_sum(d);
        prevLogit = d + bias;
    }

    float m = -1e30f, l = 0.f;
    float ax = 0.f, ay = 0.f, az = 0.f, aw = 0.f;

    const float* rp = encb + (size_t)rowStart * H_ + lane * 4;
    #pragma unroll 2
    for (int it = 0; it < ROWS_PER_WARP / 4; it++) {
        const float4 v0 = __ldcs(reinterpret_cast<const float4*>(rp));
        const float4 v1 = __ldcs(reinterpret_cast<const float4*>(rp + H_));
        const float4 v2 = __ldcs(reinterpret_cast<const float4*>(rp + 2 * H_));
        const float4 v3 = __ldcs(reinterpret_cast<const float4*>(rp + 3 * H_));
        rp += 4 * H_;
        float d0 = v0.x * wa.x + v0.y * wa.y + v0.z * wa.z + v0.w * wa.w;
        float d1 = v1.x * wa.x + v1.y * wa.y + v1.z * wa.z + v1.w * wa.w;
        float d2 = v2.x * wa.x + v2.y * wa.y + v2.z * wa.z + v2.w * wa.w;
        float d3 = v3.x * wa.x + v3.y * wa.y + v3.z * wa.z + v3.w * wa.w;
        #pragma unroll
        for (int o = 16; o; o >>= 1) {
            d0 += __shfl_xor_sync(0xffffffffu, d0, o);
            d1 += __shfl_xor_sync(0xffffffffu, d1, o);
            d2 += __shfl_xor_sync(0xffffffffu, d2, o);
            d3 += __shfl_xor_sync(0xffffffffu, d3, o);
        }
        const float l0 = prevLogit;
        const float l1 = d0 + bias;
        const float l2 = d1 + bias;
        const float l3 = d2 + bias;
        prevLogit = d3 + bias;
        const float mNew = fmaxf(fmaxf(m, fmaxf(l0, l1)), fmaxf(l2, l3));
        const float corr = __expf(m - mNew);
        const float p0   = __expf(l0 - mNew);
        const float p1   = __expf(l1 - mNew);
        const float p2   = __expf(l2 - mNew);
        const float p3   = __expf(l3 - mNew);
        l  = l * corr + p0 + p1 + p2 + p3;
        ax = ax * corr + p0 * v0.x + p1 * v1.x + p2 * v2.x + p3 * v3.x;
        ay = ay * corr + p0 * v0.y + p1 * v1.y + p2 * v2.y + p3 * v3.y;
        az = az * corr + p0 * v0.z + p1 * v1.z + p2 * v2.z + p3 * v3.z;
        aw = aw * corr + p0 * v0.w + p1 * v1.w + p2 * v2.w + p3 * v3.w;
        m = mNew;
    }

    if (lane == 0) { s_m[warp] = m; s_l[warp] = l; }
    s_acc[warp][lane * 4 + 0] = ax;
    s_acc[warp][lane * 4 + 1] = ay;
    s_acc[warp][lane * 4 + 2] = az;
    s_acc[warp][lane * 4 + 3] = aw;
    __syncthreads();

    if (tid < H_) {
        float M = s_m[0];
        #pragma unroll
        for (int w = 1; w < WARPS; w++) M = fmaxf(M, s_m[w]);
        float L = 0.f, A = 0.f;
        #pragma unroll
        for (int w = 0; w < WARPS; w++) {
            const float e = __expf(s_m[w] - M);
            L += s_l[w] * e;
            A += s_acc[w][tid] * e;
        }
        const int pi = b * CHUNKS + c;
        g_pacc[pi * H_ + tid] = A;
        if (tid == 0) { g_pm[pi] = M; g_pl[pi] = L; }
    }
}

// ---------------------------------------------------------------------------
// LSTM step v4: thread = (b, kseg). Each thread loads each activation ONCE
// (direct coalesced LDG) and computes partials for ALL 4 gates from it.
// Weights: float4 broadcast LDS. Act traffic /4, weight LDS /4 vs v3.
// ---------------------------------------------------------------------------
__device__ __forceinline__ void lstm_step(
    int h, int tid,
    const float* __restrict__ xT, const float* __restrict__ hT,   // [k][b]
    const float* __restrict__ W_ih, const float* __restrict__ W_hh,
    const float* __restrict__ b_ih, const float* __restrict__ b_hh,
    const float* __restrict__ cPrev,
    float* __restrict__ outH, float* __restrict__ outH2,
    float* __restrict__ outC, float* __restrict__ hT_out,
    float* s_w, float* s_p, float* s_gate)
{
    const int b    = tid & 63;
    const int kseg = tid >> 6;    // 0..7, each covers 32 of 256 k

    // stage weights: s_w[g*256 + k]; k<128 -> W_ih row, else W_hh row
    if (tid < 256) {
        const int g = tid >> 6;
        const int q = tid & 63;
        const float4* src = (q < 32)
            ? reinterpret_cast<const float4*>(W_ih + (g * H_ + h) * H_) + q
            : reinterpret_cast<const float4*>(W_hh + (g * H_ + h) * H_) + (q - 32);
        reinterpret_cast<float4*>(s_w)[tid] = *src;
    }
    __syncthreads();

    const float* ap = ((kseg < 4) ? (xT + kseg * 32 * B_)
                                  : (hT + (kseg - 4) * 32 * B_)) + b;
    const int kw = kseg * 32;
    float a0 = 0.f, a1 = 0.f, a2 = 0.f, a3 = 0.f;
    #pragma unroll
    for (int kk = 0; kk < 32; kk += 4) {
        const float v0 = ap[(kk + 0) * B_];
        const float v1 = ap[(kk + 1) * B_];
        const float v2 = ap[(kk + 2) * B_];
        const float v3 = ap[(kk + 3) * B_];
        const float4 w0 = *reinterpret_cast<const float4*>(&s_w[0 * 256 + kw + kk]);
        const float4 w1 = *reinterpret_cast<const float4*>(&s_w[1 * 256 + kw + kk]);
        const float4 w2 = *reinterpret_cast<const float4*>(&s_w[2 * 256 + kw + kk]);
        const float4 w3 = *reinterpret_cast<const float4*>(&s_w[3 * 256 + kw + kk]);
        a0 = fmaf(w0.x, v0, a0); a0 = fmaf(w0.y, v1, a0); a0 = fmaf(w0.z, v2, a0); a0 = fmaf(w0.w, v3, a0);
        a1 = fmaf(w1.x, v0, a1); a1 = fmaf(w1.y, v1, a1); a1 = fmaf(w1.z, v2, a1); a1 = fmaf(w1.w, v3, a1);
        a2 = fmaf(w2.x, v0, a2); a2 = fmaf(w2.y, v1, a2); a2 = fmaf(w2.z, v2, a2); a2 = fmaf(w2.w, v3, a2);
        a3 = fmaf(w3.x, v0, a3); a3 = fmaf(w3.y, v1, a3); a3 = fmaf(w3.z, v2, a3); a3 = fmaf(w3.w, v3, a3);
    }
    s_p[(0 * 8 + kseg) * B_ + b] = a0;
    s_p[(1 * 8 + kseg) * B_ + b] = a1;
    s_p[(2 * 8 + kseg) * B_ + b] = a2;
    s_p[(3 * 8 + kseg) * B_ + b] = a3;
    __syncthreads();

    if (tid < 256) {
        const int g  = tid >> 6;
        const int bb = tid & 63;
        float s = b_ih[g * H_ + h] + b_hh[g * H_ + h];
        #pragma unroll
        for (int q = 0; q < 8; q++) s += s_p[(g * 8 + q) * B_ + bb];
        s_gate[g * B_ + bb] = s;
    }
    __syncthreads();

    if (tid < B_) {
        const int bb = tid;
        const float gi = s_gate[0 * B_ + bb];
        const float gf = s_gate[1 * B_ + bb];
        const float gg = s_gate[2 * B_ + bb];
        const float go = s_gate[3 * B_ + bb];
        const float cp = cPrev[bb * H_ + h];
        const float cN = sigm(gf) * cp + sigm(gi) * tanhf(gg);
        const float hN = sigm(go) * tanhf(cN);
        outH[bb * H_ + h] = hN;
        if (outH2) outH2[bb * H_ + h] = hN;
        outC[bb * H_ + h] = cN;
        if (hT_out) hT_out[h * B_ + bb] = hN;
    }
}

// ---------------------------------------------------------------------------
// Fused tail: combine -> xin -> LSTM0 -> LSTM1, small static smem.
// grid = 128 x 512, single wave -> software grid barriers safe.
// out layout: [h2 (B,H)] [h1] [h2] [c1] [c2]
// ---------------------------------------------------------------------------
__global__ __launch_bounds__(512, 1)
void tail_fused_kernel(const float* __restrict__ input,
                       const float* __restrict__ h0,
                       const float* __restrict__ c0,
                       const float* __restrict__ inp_W,
                       const float* __restrict__ inp_b,
                       const float* __restrict__ W_ih0,
                       const float* __restrict__ W_hh0,
                       const float* __restrict__ b_ih0,
                       const float* __restrict__ b_hh0,
                       const float* __restrict__ W_ih1,
                       const float* __restrict__ W_hh1,
                       const float* __restrict__ b_ih1,
                       const float* __restrict__ b_hh1,
                       float* __restrict__ out)
{
    __shared__ __align__(16) float s_w[4 * 256];      // 4 KB
    __shared__ float s_p[4 * 8 * B_];                 // 8 KB
    __shared__ float s_gate[4 * B_];                  // 1 KB

    const int blk = blockIdx.x;
    const int tid = threadIdx.x;

    // ---- Step A: combine (blocks 0..63, threads 0..255) ----
    if (blk < B_ && tid < H_ + I_) {
        const int b = blk;
        const int k = tid;
        if (k < H_) {
            float M = g_pm[b * CHUNKS + 0];
            #pragma unroll
            for (int cc = 1; cc < CHUNKS; cc++) M = fmaxf(M, g_pm[b * CHUNKS + cc]);
            float L = 0.f, A = 0.f;
            #pragma unroll
            for (int cc = 0; cc < CHUNKS; cc++) {
                const float e = __expf(g_pm[b * CHUNKS + cc] - M);
                L += g_pl[b * CHUNKS + cc] * e;
                A += g_pacc[(b * CHUNKS + cc) * H_ + k] * e;
            }
            g_xcatT[k * B_ + b] = A / L;
            g_h0T0[k * B_ + b] = h0[(0 * B_ + b) * H_ + k];
            g_h0T1[k * B_ + b] = h0[(1 * B_ + b) * H_ + k];
        } else {
            g_xcatT[k * B_ + b] = input[b * I_ + (k - H_)];
        }
    }
    grid_barrier(0);

    // ---- Step B: xin. block = j, thread = (b, kseg); acts direct from L2 ----
    {
        const int j    = blk;
        const int b    = tid & 63;
        const int kseg = tid >> 6;      // 8 segments x 32 k

        if (tid < H_ + I_) s_w[tid] = inp_W[j * (H_ + I_) + tid];
        __syncthreads();

        const float* wp = s_w + kseg * 32;
        const float* ap = g_xcatT + kseg * 32 * B_ + b;
        float acc = 0.f;
        #pragma unroll
        for (int kk = 0; kk < 32; kk += 8) {
            float v0 = ap[(kk + 0) * B_];
            float v1 = ap[(kk + 1) * B_];
            float v2 = ap[(kk + 2) * B_];
            float v3 = ap[(kk + 3) * B_];
            float v4 = ap[(kk + 4) * B_];
            float v5 = ap[(kk + 5) * B_];
            float v6 = ap[(kk + 6) * B_];
            float v7 = ap[(kk + 7) * B_];
            acc = fmaf(wp[kk + 0], v0, acc);
            acc = fmaf(wp[kk + 1], v1, acc);
            acc = fmaf(wp[kk + 2], v2, acc);
            acc = fmaf(wp[kk + 3], v3, acc);
            acc = fmaf(wp[kk + 4], v4, acc);
            acc = fmaf(wp[kk + 5], v5, acc);
            acc = fmaf(wp[kk + 6], v6, acc);
            acc = fmaf(wp[kk + 7], v7, acc);
        }
        s_p[kseg * B_ + b] = acc;
        __syncthreads();

        if (tid < B_) {
            float s = inp_b[j];
            #pragma unroll
            for (int q = 0; q < 8; q++) s += s_p[q * B_ + tid];
            g_xinT[j * B_ + tid] = s;
        }
    }
    grid_barrier(1);

    // ---- Step C: LSTM layer 0 (block = h) ----
    lstm_step(blk, tid, g_xinT, g_h0T0, W_ih0, W_hh0, b_ih0, b_hh0,
              c0 + 0 * B_ * H_,
              out + 1 * B_ * H_, nullptr, out + 3 * B_ * H_, g_h1T,
              s_w, s_p, s_gate);
    grid_barrier(2);

    // ---- Step D: LSTM layer 1 (block = h) ----
    lstm_step(blk, tid, g_h1T, g_h0T1, W_ih1, W_hh1, b_ih1, b_hh1,
              c0 + 1 * B_ * H_,
              out + 0 * B_ * H_, out + 2 * B_ * H_, out + 4 * B_ * H_, nullptr,
              s_w, s_p, s_gate);
}

extern "C" void kernel_launch(void* const* d_in, const int* in_sizes, int n_in,
                              void* d_out, int out_size) {
    const float* input  = (const float*)d_in[0];
    const float* h0     = (const float*)d_in[1];
    const float* c0     = (const float*)d_in[2];
    const float* enc    = (const float*)d_in[3];
    const float* attW   = (const float*)d_in[4];
    const float* attB   = (const float*)d_in[5];
    const float* inp_W  = (const float*)d_in[6];
    const float* inp_b  = (const float*)d_in[7];
    const float* W_ih0  = (const float*)d_in[8];
    const float* W_hh0  = (const float*)d_in[9];
    const float* b_ih0  = (const float*)d_in[10];
    const float* b_hh0  = (const float*)d_in[11];
    const float* W_ih1  = (const float*)d_in[12];
    const float* W_hh1  = (const float*)d_in[13];
    const float* b_ih1  = (const float*)d_in[14];
    const float* b_hh1  = (const float*)d_in[15];
    float* out = (float*)d_out;

    dim3 grid1(CHUNKS, B_);
    attn_partial_kernel<<<grid1, 256>>>(enc, h0, c0, attW, attB);
    tail_fused_kernel<<<TAIL_BLOCKS, 512>>>(input, h0, c0, inp_W, inp_b,
                                            W_ih0, W_hh0, b_ih0, b_hh0,
                                            W_ih1, W_hh1, b_ih1, b_hh1, out);
}